// round 2
// baseline (speedup 1.0000x reference)
#include <cuda_runtime.h>
#include <cuda_bf16.h>
#include <math.h>

// ---------------------------------------------------------------------------
// SeFT network:
//  1) gather nonzero (t, col, val) per patient (row-major nonzero order)
//  2) per-observation MLP 34->128->128->128 (enc) and K projection 128->128
//  3) last-position query (pad-enc unless len==Lmax), masked softmax attention
//     of the last position over valid keys, weighted sum of enc per head.
// Output: (B, 4*128) fp32.
// ---------------------------------------------------------------------------

#define BMAX   32
#define LSTRIDE 2048      // max observations per patient we support
#define HID    128
#define NIN    34

__device__ float g_St[BMAX * LSTRIDE];
__device__ float g_Sc[BMAX * LSTRIDE];
__device__ float g_Sx[BMAX * LSTRIDE];
__device__ int   g_lens[BMAX];
__device__ int   g_maxlen;                      // idempotent atomicMax
__device__ float g_lastfeat[BMAX * 3];          // (t, col, val) of query position
__device__ float g_enc[(size_t)BMAX * LSTRIDE * HID];
__device__ float g_k  [(size_t)BMAX * LSTRIDE * HID];
__device__ float g_q  [BMAX * HID];

// ---------------------------------------------------------------------------
// Kernel 1: gather. One block per patient; scan all R*V mask entries in
// row-major order, keep entries whose row belongs to this patient. Positions
// come from a block-wide prefix sum over per-thread contiguous chunks.
// ---------------------------------------------------------------------------
__global__ void k_gather(const float* __restrict__ times,
                         const int*   __restrict__ time_ptr,
                         const float* __restrict__ X,
                         const int*   __restrict__ M,
                         const int*   __restrict__ obs_idx,
                         int R, int V, int n_times)
{
    int b = blockIdx.x;
    int t = threadIdx.x;
    int total = R * V;
    int per = (total + 255) / 256;
    int s = t * per;
    int e = min(s + per, total);

    int cnt = 0;
    {
        int r = (s < total) ? (s / V) : 0;
        int c = (s < total) ? (s - r * V) : 0;
        for (int f = s; f < e; f++) {
            if (obs_idx[r] == b && M[f] != 0) cnt++;
            if (++c == V) { c = 0; r++; }
        }
    }

    __shared__ int sc[256];
    sc[t] = cnt;
    __syncthreads();
    for (int off = 1; off < 256; off <<= 1) {
        int v = (t >= off) ? sc[t - off] : 0;
        __syncthreads();
        sc[t] += v;
        __syncthreads();
    }
    int pos = sc[t] - cnt;
    int tot = sc[255];

    {
        int r = (s < total) ? (s / V) : 0;
        int c = (s < total) ? (s - r * V) : 0;
        for (int f = s; f < e; f++) {
            if (obs_idx[r] == b && M[f] != 0) {
                if (pos < LSTRIDE) {
                    // t_arr[r] = times[j] with time_ptr[j] <= r < time_ptr[j+1]
                    int lo = 0, hi = n_times - 1;
                    while (lo < hi) {
                        int mid = (lo + hi + 1) >> 1;
                        if (time_ptr[mid] <= r) lo = mid; else hi = mid - 1;
                    }
                    g_St[b * LSTRIDE + pos] = times[lo];
                    g_Sc[b * LSTRIDE + pos] = (float)c;
                    g_Sx[b * LSTRIDE + pos] = X[f];
                }
                pos++;
            }
            if (++c == V) { c = 0; r++; }
        }
    }

    if (t == 0) {
        int L = min(tot, LSTRIDE);
        g_lens[b] = L;
        atomicMax(&g_maxlen, L);
    }
}

// ---------------------------------------------------------------------------
// Kernel 2: pick the query-position features per patient (pad = zeros unless
// the patient actually fills position Lmax-1).
// ---------------------------------------------------------------------------
__global__ void k_last(int B)
{
    int b = threadIdx.x;
    if (b >= B) return;
    int L = g_maxlen;
    float ft = 0.f, fc = 0.f, fx = 0.f;
    if (L >= 1 && g_lens[b] == L) {
        ft = g_St[b * LSTRIDE + L - 1];
        fc = g_Sc[b * LSTRIDE + L - 1];
        fx = g_Sx[b * LSTRIDE + L - 1];
    }
    g_lastfeat[b * 3 + 0] = ft;
    g_lastfeat[b * 3 + 1] = fc;
    g_lastfeat[b * 3 + 2] = fx;
}

// ---------------------------------------------------------------------------
// Dense layer helper: thread tid computes out[o][tid] for 32 observations.
// Weights row tid streamed as float4 (L1-resident), activations broadcast
// from shared memory. 32 independent accumulators -> FMA-pipe bound.
// ---------------------------------------------------------------------------
__device__ __forceinline__ void gemm128(const float* __restrict__ W,
                                        const float* __restrict__ bias,
                                        const float* sin_, float acc[32], int tid)
{
    float bb = __ldg(&bias[tid]);
#pragma unroll
    for (int o = 0; o < 32; o++) acc[o] = bb;
    const float4* Wr = (const float4*)(W + tid * HID);
    for (int k0 = 0; k0 < HID / 4; k0++) {
        float4 w4 = __ldg(&Wr[k0]);
#pragma unroll
        for (int o = 0; o < 32; o++) {
            float4 h4 = *(const float4*)(sin_ + o * HID + k0 * 4);
            acc[o] = fmaf(w4.x, h4.x, acc[o]);
            acc[o] = fmaf(w4.y, h4.y, acc[o]);
            acc[o] = fmaf(w4.z, h4.z, acc[o]);
            acc[o] = fmaf(w4.w, h4.w, acc[o]);
        }
    }
}

__device__ __forceinline__ void features_to_smem(float tval, float c, float x,
                                                 float* sf, int o)
{
#pragma unroll
    for (int i = 0; i < 16; i++) {
        float ts = powf(100.0f, (float)i * (1.0f / 15.0f));
        float st = tval / ts;
        float sn, cs;
        sincosf(st, &sn, &cs);
        sf[o * NIN + i]      = sn;
        sf[o * NIN + 16 + i] = cs;
    }
    sf[o * NIN + 32] = c;
    sf[o * NIN + 33] = x;
}

// ---------------------------------------------------------------------------
// Kernel 3: MLP + K projection for tiles of 32 observations.
// grid = B * (LSTRIDE/32), block = 128.
// ---------------------------------------------------------------------------
__global__ __launch_bounds__(128) void k_mlp(
    const float* __restrict__ W0, const float* __restrict__ b0,
    const float* __restrict__ W1, const float* __restrict__ b1,
    const float* __restrict__ W2, const float* __restrict__ b2,
    const float* __restrict__ Wk, const float* __restrict__ bk)
{
    int b  = blockIdx.x >> 6;           // / 64 tiles
    int lt = blockIdx.x & 63;
    int len = g_lens[b];
    int l0 = lt * 32;
    if (l0 >= len) return;
    int nv = min(32, len - l0);

    __shared__ __align__(16) float sf[32 * NIN];
    __shared__ __align__(16) float sA[32 * HID];
    __shared__ __align__(16) float sB[32 * HID];
    int tid = threadIdx.x;

    if (tid < 32) {
        int o = tid;
        float tval = 0.f, c = 0.f, x = 0.f;
        if (o < nv) {
            tval = g_St[b * LSTRIDE + l0 + o];
            c    = g_Sc[b * LSTRIDE + l0 + o];
            x    = g_Sx[b * LSTRIDE + l0 + o];
        }
        features_to_smem(tval, c, x, sf, o);
    }
    __syncthreads();

    float acc[32];

    // layer 0: 34 -> 128, relu
    {
        float bb = __ldg(&b0[tid]);
#pragma unroll
        for (int o = 0; o < 32; o++) acc[o] = bb;
        for (int i = 0; i < NIN; i++) {
            float w = __ldg(&W0[tid * NIN + i]);
#pragma unroll
            for (int o = 0; o < 32; o++) acc[o] = fmaf(w, sf[o * NIN + i], acc[o]);
        }
#pragma unroll
        for (int o = 0; o < 32; o++) sA[o * HID + tid] = fmaxf(acc[o], 0.f);
    }
    __syncthreads();

    // layer 1: 128 -> 128, relu
    gemm128(W1, b1, sA, acc, tid);
#pragma unroll
    for (int o = 0; o < 32; o++) sB[o * HID + tid] = fmaxf(acc[o], 0.f);
    __syncthreads();

    // layer 2 (enc): 128 -> 128, linear; keep in shared + write global
    gemm128(W2, b2, sB, acc, tid);
#pragma unroll
    for (int o = 0; o < 32; o++) {
        sA[o * HID + tid] = acc[o];
        if (o < nv)
            g_enc[(size_t)(b * LSTRIDE + l0 + o) * HID + tid] = acc[o];
    }
    __syncthreads();

    // K projection: 128 -> 128
    gemm128(Wk, bk, sA, acc, tid);
#pragma unroll
    for (int o = 0; o < 32; o++)
        if (o < nv)
            g_k[(size_t)(b * LSTRIDE + l0 + o) * HID + tid] = acc[o];
}

// ---------------------------------------------------------------------------
// Kernel 4: enc of the query position for all B patients + Q projection.
// One block, 128 threads, 32 "observations" (one per patient).
// ---------------------------------------------------------------------------
__global__ __launch_bounds__(128) void k_lastmlp(
    const float* __restrict__ W0, const float* __restrict__ b0,
    const float* __restrict__ W1, const float* __restrict__ b1,
    const float* __restrict__ W2, const float* __restrict__ b2,
    const float* __restrict__ Wq, const float* __restrict__ bq,
    int B)
{
    __shared__ __align__(16) float sf[32 * NIN];
    __shared__ __align__(16) float sA[32 * HID];
    __shared__ __align__(16) float sB[32 * HID];
    int tid = threadIdx.x;

    if (tid < 32) {
        int o = tid;
        float tval = 0.f, c = 0.f, x = 0.f;
        if (o < B) {
            tval = g_lastfeat[o * 3 + 0];
            c    = g_lastfeat[o * 3 + 1];
            x    = g_lastfeat[o * 3 + 2];
        }
        features_to_smem(tval, c, x, sf, o);
    }
    __syncthreads();

    float acc[32];
    {
        float bb = __ldg(&b0[tid]);
#pragma unroll
        for (int o = 0; o < 32; o++) acc[o] = bb;
        for (int i = 0; i < NIN; i++) {
            float w = __ldg(&W0[tid * NIN + i]);
#pragma unroll
            for (int o = 0; o < 32; o++) acc[o] = fmaf(w, sf[o * NIN + i], acc[o]);
        }
#pragma unroll
        for (int o = 0; o < 32; o++) sA[o * HID + tid] = fmaxf(acc[o], 0.f);
    }
    __syncthreads();

    gemm128(W1, b1, sA, acc, tid);
#pragma unroll
    for (int o = 0; o < 32; o++) sB[o * HID + tid] = fmaxf(acc[o], 0.f);
    __syncthreads();

    gemm128(W2, b2, sB, acc, tid);
#pragma unroll
    for (int o = 0; o < 32; o++) sA[o * HID + tid] = acc[o];
    __syncthreads();

    gemm128(Wq, bq, sA, acc, tid);
#pragma unroll
    for (int o = 0; o < 32; o++)
        if (o < B) g_q[o * HID + tid] = acc[o];
}

// ---------------------------------------------------------------------------
// Kernel 5: masked softmax attention of the last position over valid keys,
// then weighted sum of enc. One block per patient, 512 threads.
// out[b][h*128 + e]
// ---------------------------------------------------------------------------
__global__ __launch_bounds__(512) void k_attn(float* __restrict__ out)
{
    int b = blockIdx.x;
    int t = threadIdx.x;
    int len = min(g_lens[b], LSTRIDE);

    __shared__ __align__(16) float sq[HID];
    __shared__ float se[LSTRIDE * 4];   // 32 KB
    __shared__ float sred[512 * 4];     // 8 KB

    if (t < HID) sq[t] = g_q[b * HID + t];
    __syncthreads();

    if (len == 0) { out[b * 512 + t] = 0.f; return; }

    const float scale = 0.17677669529663687f; // 1/sqrt(32)
    float lmx[4] = {-1e30f, -1e30f, -1e30f, -1e30f};

    for (int l = t; l < len; l += 512) {
        const float* kr = &g_k[(size_t)(b * LSTRIDE + l) * HID];
#pragma unroll
        for (int h = 0; h < 4; h++) {
            const float4* q4 = (const float4*)(sq + h * 32);
            const float4* k4 = (const float4*)(kr + h * 32);
            float s = 0.f;
#pragma unroll
            for (int j = 0; j < 8; j++) {
                float4 a = q4[j];
                float4 bb = __ldg(&k4[j]);
                s += a.x * bb.x + a.y * bb.y + a.z * bb.z + a.w * bb.w;
            }
            s *= scale;
            se[l * 4 + h] = s;
            lmx[h] = fmaxf(lmx[h], s);
        }
    }

#pragma unroll
    for (int h = 0; h < 4; h++) sred[t * 4 + h] = lmx[h];
    __syncthreads();
    for (int s = 256; s > 0; s >>= 1) {
        if (t < s) {
#pragma unroll
            for (int h = 0; h < 4; h++)
                sred[t * 4 + h] = fmaxf(sred[t * 4 + h], sred[(t + s) * 4 + h]);
        }
        __syncthreads();
    }
    float mx[4];
#pragma unroll
    for (int h = 0; h < 4; h++) mx[h] = sred[h];
    __syncthreads();

    float lsm[4] = {0.f, 0.f, 0.f, 0.f};
    for (int l = t; l < len; l += 512) {
#pragma unroll
        for (int h = 0; h < 4; h++) {
            float e = expf(se[l * 4 + h] - mx[h]);
            se[l * 4 + h] = e;
            lsm[h] += e;
        }
    }
#pragma unroll
    for (int h = 0; h < 4; h++) sred[t * 4 + h] = lsm[h];
    __syncthreads();
    for (int s = 256; s > 0; s >>= 1) {
        if (t < s) {
#pragma unroll
            for (int h = 0; h < 4; h++)
                sred[t * 4 + h] += sred[(t + s) * 4 + h];
        }
        __syncthreads();
    }

    int h = t >> 7;
    int e = t & 127;
    float inv = 1.f / sred[h];

    float acc = 0.f;
    const float* encb = &g_enc[(size_t)(b * LSTRIDE) * HID + e];
    for (int l = 0; l < len; l++)
        acc = fmaf(se[l * 4 + h], __ldg(&encb[(size_t)l * HID]), acc);

    out[b * 512 + t] = acc * inv;
}

// ---------------------------------------------------------------------------
extern "C" void kernel_launch(void* const* d_in, const int* in_sizes, int n_in,
                              void* d_out, int out_size)
{
    const float* times    = (const float*)d_in[0];
    const int*   time_ptr = (const int*)  d_in[1];
    const float* X        = (const float*)d_in[2];
    const int*   M        = (const int*)  d_in[3];
    const int*   obs_idx  = (const int*)  d_in[4];
    // d_in[5] = pat_idx (only its length matters)
    const float* W0 = (const float*)d_in[6];
    const float* b0 = (const float*)d_in[7];
    const float* W1 = (const float*)d_in[8];
    const float* b1 = (const float*)d_in[9];
    const float* W2 = (const float*)d_in[10];
    const float* b2 = (const float*)d_in[11];
    const float* Wq = (const float*)d_in[12];
    const float* bq = (const float*)d_in[13];
    const float* Wk = (const float*)d_in[14];
    const float* bk = (const float*)d_in[15];

    int R       = in_sizes[0];
    int n_times = in_sizes[0];
    int V       = in_sizes[2] / R;
    int B       = in_sizes[5];

    k_gather<<<B, 256>>>(times, time_ptr, X, M, obs_idx, R, V, n_times);
    k_last<<<1, 32>>>(B);
    k_mlp<<<B * (LSTRIDE / 32), 128>>>(W0, b0, W1, b1, W2, b2, Wk, bk);
    k_lastmlp<<<1, 128>>>(W0, b0, W1, b1, W2, b2, Wq, bq, B);
    k_attn<<<B, 512>>>((float*)d_out);
}

// round 3
// speedup vs baseline: 1.1664x; 1.1664x over previous
#include <cuda_runtime.h>
#include <math.h>

// ---------------------------------------------------------------------------
// SeFT network, round 2:
//  - gather (unchanged from R1)
//  - fused per-observation MLP 34->128->128->128 + K projection using packed
//    fp32x2 FFMA (activations in [k][obs] smem layout, obs paired in f32x2)
//  - query-path MLP folded into k_mlp as block 0 (Wq instead of Wk)
//  - K written transposed (g_kT[b][e][l]) for coalesced attention scores
//  - attention: coalesced score pass + single-read weighted enc sum
// ---------------------------------------------------------------------------

#define BMAX    32
#define LSTRIDE 2048
#define HID     128
#define NIN     34
#define ASTR    36          // obs-row stride (floats): conflict-free + 16B aligned

typedef unsigned long long ull;

__device__ float g_St[BMAX * LSTRIDE];
__device__ float g_Sc[BMAX * LSTRIDE];
__device__ float g_Sx[BMAX * LSTRIDE];
__device__ int   g_lens[BMAX];
__device__ int   g_maxlen;
__device__ float g_lastfeat[BMAX * 3];
__device__ float g_enc[(size_t)BMAX * LSTRIDE * HID];   // [b][l][e]
__device__ float g_kT [(size_t)BMAX * HID * LSTRIDE];   // [b][e][l]
__device__ float g_q  [BMAX * HID];

// ---- packed fp32x2 helpers -------------------------------------------------
__device__ __forceinline__ ull pack2(float x, float y) {
    ull r;
    asm("mov.b64 %0, {%1, %2};" : "=l"(r) : "f"(x), "f"(y));
    return r;
}
__device__ __forceinline__ void unpack2(ull v, float& lo, float& hi) {
    asm("mov.b64 {%0, %1}, %2;" : "=f"(lo), "=f"(hi) : "l"(v));
}
__device__ __forceinline__ ull ffma2(ull a, ull b, ull c) {
    ull d;
    asm("fma.rn.f32x2 %0, %1, %2, %3;" : "=l"(d) : "l"(a), "l"(b), "l"(c));
    return d;
}

// ---------------------------------------------------------------------------
// Kernel 1: gather (unchanged from R1 — known correct)
// ---------------------------------------------------------------------------
__global__ void k_gather(const float* __restrict__ times,
                         const int*   __restrict__ time_ptr,
                         const float* __restrict__ X,
                         const int*   __restrict__ M,
                         const int*   __restrict__ obs_idx,
                         int R, int V, int n_times)
{
    int b = blockIdx.x;
    int t = threadIdx.x;
    int total = R * V;
    int per = (total + 255) / 256;
    int s = t * per;
    int e = min(s + per, total);

    int cnt = 0;
    {
        int r = (s < total) ? (s / V) : 0;
        int c = (s < total) ? (s - r * V) : 0;
        for (int f = s; f < e; f++) {
            if (obs_idx[r] == b && M[f] != 0) cnt++;
            if (++c == V) { c = 0; r++; }
        }
    }

    __shared__ int sc[256];
    sc[t] = cnt;
    __syncthreads();
    for (int off = 1; off < 256; off <<= 1) {
        int v = (t >= off) ? sc[t - off] : 0;
        __syncthreads();
        sc[t] += v;
        __syncthreads();
    }
    int pos = sc[t] - cnt;
    int tot = sc[255];

    {
        int r = (s < total) ? (s / V) : 0;
        int c = (s < total) ? (s - r * V) : 0;
        for (int f = s; f < e; f++) {
            if (obs_idx[r] == b && M[f] != 0) {
                if (pos < LSTRIDE) {
                    int lo = 0, hi = n_times - 1;
                    while (lo < hi) {
                        int mid = (lo + hi + 1) >> 1;
                        if (time_ptr[mid] <= r) lo = mid; else hi = mid - 1;
                    }
                    g_St[b * LSTRIDE + pos] = times[lo];
                    g_Sc[b * LSTRIDE + pos] = (float)c;
                    g_Sx[b * LSTRIDE + pos] = X[f];
                }
                pos++;
            }
            if (++c == V) { c = 0; r++; }
        }
    }

    if (t == 0) {
        int L = min(tot, LSTRIDE);
        g_lens[b] = L;
        atomicMax(&g_maxlen, L);
    }
}

// ---------------------------------------------------------------------------
// Kernel 2: query-position features per patient
// ---------------------------------------------------------------------------
__global__ void k_last(int B)
{
    int b = threadIdx.x;
    if (b >= B) return;
    int L = g_maxlen;
    float ft = 0.f, fc = 0.f, fx = 0.f;
    if (L >= 1 && g_lens[b] == L) {
        ft = g_St[b * LSTRIDE + L - 1];
        fc = g_Sc[b * LSTRIDE + L - 1];
        fx = g_Sx[b * LSTRIDE + L - 1];
    }
    g_lastfeat[b * 3 + 0] = ft;
    g_lastfeat[b * 3 + 1] = fc;
    g_lastfeat[b * 3 + 2] = fx;
}

// ---------------------------------------------------------------------------
// 128->128 dense layer, f32x2. Thread tid owns output row `tid`.
// sIn is [k][obs] with row stride ASTR floats. acc[j] holds obs (2j, 2j+1).
// ---------------------------------------------------------------------------
__device__ __forceinline__ void gemm128x2(const float* __restrict__ W,
                                          const float* __restrict__ bias,
                                          const float* sIn, ull acc[16], int tid)
{
    float bb = __ldg(&bias[tid]);
    ull b2 = pack2(bb, bb);
#pragma unroll
    for (int j = 0; j < 16; j++) acc[j] = b2;
    const float4* Wr = (const float4*)(W + tid * HID);
#pragma unroll 4
    for (int k0 = 0; k0 < HID / 4; k0++) {
        float4 w4 = __ldg(&Wr[k0]);
        const float* r0 = sIn + (k0 * 4) * ASTR;
#pragma unroll
        for (int j = 0; j < 4; j++) {
            float wj = (j == 0) ? w4.x : (j == 1) ? w4.y : (j == 2) ? w4.z : w4.w;
            ull w2 = pack2(wj, wj);
            const ulonglong2* row = (const ulonglong2*)(r0 + j * ASTR);
#pragma unroll
            for (int p = 0; p < 8; p++) {
                ulonglong2 v = row[p];
                acc[2 * p]     = ffma2(v.x, w2, acc[2 * p]);
                acc[2 * p + 1] = ffma2(v.y, w2, acc[2 * p + 1]);
            }
        }
    }
}

// ---------------------------------------------------------------------------
// Kernel 3: fused MLP + projection, 32-obs tiles, f32x2.
// Block 0 is the query path (lastfeat -> enc -> Wq -> g_q).
// Blocks 1.. : (b, tile) -> enc + transposed K.
// ---------------------------------------------------------------------------
__global__ __launch_bounds__(128) void k_mlp(
    const float* __restrict__ W0, const float* __restrict__ b0,
    const float* __restrict__ W1, const float* __restrict__ b1,
    const float* __restrict__ W2, const float* __restrict__ b2,
    const float* __restrict__ Wk, const float* __restrict__ bk,
    const float* __restrict__ Wq, const float* __restrict__ bq,
    int B)
{
    __shared__ __align__(16) float sf[NIN * ASTR];
    __shared__ __align__(16) float sA[HID * ASTR];
    __shared__ __align__(16) float sB[HID * ASTR];   // also aliased as W0 smem copy
    float* sW0 = sB;                                  // 4352 <= 4608 floats

    int tid = threadIdx.x;
    bool special = (blockIdx.x == 0);
    int b = 0, l0 = 0, nv = 0;
    if (!special) {
        int bi = blockIdx.x - 1;
        b = bi >> 6;
        int lt = bi & 63;
        int len = g_lens[b];
        l0 = lt * 32;
        if (l0 >= len) return;
        nv = min(32, len - l0);
    } else {
        nv = min(B, 32);
    }

    // cooperative coalesced preload of W0 into smem
    {
        const float4* src = (const float4*)W0;
        float4* dst = (float4*)sW0;
        for (int i = tid; i < (HID * NIN) / 4; i += 128) dst[i] = __ldg(&src[i]);
    }

    // features into [k][obs] layout
    if (tid < 32) {
        int o = tid;
        float tv = 0.f, cv = 0.f, xv = 0.f;
        if (o < nv) {
            if (special) {
                tv = g_lastfeat[o * 3 + 0];
                cv = g_lastfeat[o * 3 + 1];
                xv = g_lastfeat[o * 3 + 2];
            } else {
                tv = g_St[b * LSTRIDE + l0 + o];
                cv = g_Sc[b * LSTRIDE + l0 + o];
                xv = g_Sx[b * LSTRIDE + l0 + o];
            }
        }
#pragma unroll
        for (int i = 0; i < 16; i++) {
            float ts = powf(100.0f, (float)i * (1.0f / 15.0f));
            float sn, cs;
            sincosf(tv / ts, &sn, &cs);
            sf[i * ASTR + o]        = sn;
            sf[(16 + i) * ASTR + o] = cs;
        }
        sf[32 * ASTR + o] = cv;
        sf[33 * ASTR + o] = xv;
    }
    __syncthreads();

    ull acc[16];

    // ---- layer 0: 34 -> 128, relu ----
    {
        float bb = __ldg(&b0[tid]);
        ull b2 = pack2(bb, bb);
#pragma unroll
        for (int j = 0; j < 16; j++) acc[j] = b2;
#pragma unroll 2
        for (int k = 0; k < NIN; k++) {
            float w = sW0[tid * NIN + k];
            ull w2 = pack2(w, w);
            const ulonglong2* row = (const ulonglong2*)(sf + k * ASTR);
#pragma unroll
            for (int p = 0; p < 8; p++) {
                ulonglong2 v = row[p];
                acc[2 * p]     = ffma2(v.x, w2, acc[2 * p]);
                acc[2 * p + 1] = ffma2(v.y, w2, acc[2 * p + 1]);
            }
        }
        float* dst = sA + tid * ASTR;
#pragma unroll
        for (int j = 0; j < 16; j++) {
            float lo, hi; unpack2(acc[j], lo, hi);
            dst[2 * j]     = fmaxf(lo, 0.f);
            dst[2 * j + 1] = fmaxf(hi, 0.f);
        }
    }
    __syncthreads();

    // ---- layer 1: 128 -> 128, relu ---- (overwrites sW0 alias; L0 is done)
    gemm128x2(W1, b1, sA, acc, tid);
    {
        float* dst = sB + tid * ASTR;
#pragma unroll
        for (int j = 0; j < 16; j++) {
            float lo, hi; unpack2(acc[j], lo, hi);
            dst[2 * j]     = fmaxf(lo, 0.f);
            dst[2 * j + 1] = fmaxf(hi, 0.f);
        }
    }
    __syncthreads();

    // ---- layer 2 (enc): 128 -> 128, linear ----
    gemm128x2(W2, b2, sB, acc, tid);
    {
        float v[32];
#pragma unroll
        for (int j = 0; j < 16; j++) unpack2(acc[j], v[2 * j], v[2 * j + 1]);
        float* dst = sA + tid * ASTR;
#pragma unroll
        for (int o = 0; o < 32; o++) dst[o] = v[o];
        if (!special) {
            for (int o = 0; o < nv; o++)
                g_enc[((size_t)b * LSTRIDE + l0 + o) * HID + tid] = v[o];
        }
    }
    __syncthreads();

    // ---- projection: Wk (normal) or Wq (special) ----
    gemm128x2(special ? Wq : Wk, special ? bq : bk, sA, acc, tid);
    {
        float v[32];
#pragma unroll
        for (int j = 0; j < 16; j++) unpack2(acc[j], v[2 * j], v[2 * j + 1]);
        if (special) {
            for (int o = 0; o < nv; o++) g_q[o * HID + tid] = v[o];
        } else {
            float* gk = g_kT + ((size_t)b * HID + tid) * LSTRIDE + l0;
#pragma unroll
            for (int o = 0; o < 32; o += 4) {
                if (o + 4 <= nv) {
                    *(float4*)(gk + o) = make_float4(v[o], v[o + 1], v[o + 2], v[o + 3]);
                } else {
                    for (int j = 0; j < 4; j++)
                        if (o + j < nv) gk[o + j] = v[o + j];
                }
            }
        }
    }
}

// ---------------------------------------------------------------------------
// Kernel 4: attention of the last position. One block per patient, 512 thr.
// Phase 1: scores via transposed K (coalesced over l).
// Phase 2: weighted enc sum, each enc element read once.
// ---------------------------------------------------------------------------
__global__ __launch_bounds__(512) void k_attn(float* __restrict__ out)
{
    int b = blockIdx.x;
    int t = threadIdx.x;
    int len = min(g_lens[b], LSTRIDE);

    __shared__ __align__(16) float sq[HID];
    __shared__ __align__(16) float se[LSTRIDE * 4];   // scores/exp; later partials
    __shared__ float sred[512 * 4];

    if (t < HID) sq[t] = g_q[b * HID + t];
    __syncthreads();

    if (len == 0) { out[b * 512 + t] = 0.f; return; }

    const float scale = 0.17677669529663687f; // 1/sqrt(32)

    // ---- phase 1: scores. warp w covers l in [w*128 + lane*4, +3] ----
    {
        int w = t >> 5, lane = t & 31;
        int l0 = w * 128 + lane * 4;
        if (l0 < len) {
            ull a2[8]; // [h*2 + pair]: pair0 = (l0,l0+1), pair1 = (l0+2,l0+3)
#pragma unroll
            for (int j = 0; j < 8; j++) a2[j] = 0ull;
            const float* kbase = g_kT + (size_t)b * HID * LSTRIDE + l0;
#pragma unroll
            for (int h = 0; h < 4; h++) {
#pragma unroll 8
                for (int e2 = 0; e2 < 32; e2++) {
                    int e = h * 32 + e2;
                    float qv = sq[e];
                    ull q2 = pack2(qv, qv);
                    ulonglong2 kv = *(const ulonglong2*)(kbase + (size_t)e * LSTRIDE);
                    a2[h * 2]     = ffma2(kv.x, q2, a2[h * 2]);
                    a2[h * 2 + 1] = ffma2(kv.y, q2, a2[h * 2 + 1]);
                }
            }
#pragma unroll
            for (int h = 0; h < 4; h++) {
                float s0, s1, s2, s3;
                unpack2(a2[h * 2], s0, s1);
                unpack2(a2[h * 2 + 1], s2, s3);
                if (l0 + 0 < len) se[(l0 + 0) * 4 + h] = s0 * scale;
                if (l0 + 1 < len) se[(l0 + 1) * 4 + h] = s1 * scale;
                if (l0 + 2 < len) se[(l0 + 2) * 4 + h] = s2 * scale;
                if (l0 + 3 < len) se[(l0 + 3) * 4 + h] = s3 * scale;
            }
        }
    }
    __syncthreads();

    // ---- max reduction ----
    float lmx[4] = {-1e30f, -1e30f, -1e30f, -1e30f};
    for (int l = t; l < len; l += 512) {
#pragma unroll
        for (int h = 0; h < 4; h++) lmx[h] = fmaxf(lmx[h], se[l * 4 + h]);
    }
#pragma unroll
    for (int h = 0; h < 4; h++) sred[t * 4 + h] = lmx[h];
    __syncthreads();
    for (int s = 256; s > 0; s >>= 1) {
        if (t < s) {
#pragma unroll
            for (int h = 0; h < 4; h++)
                sred[t * 4 + h] = fmaxf(sred[t * 4 + h], sred[(t + s) * 4 + h]);
        }
        __syncthreads();
    }
    float mx[4];
#pragma unroll
    for (int h = 0; h < 4; h++) mx[h] = sred[h];
    __syncthreads();

    // ---- exp + sum reduction ----
    float lsm[4] = {0.f, 0.f, 0.f, 0.f};
    for (int l = t; l < len; l += 512) {
#pragma unroll
        for (int h = 0; h < 4; h++) {
            float e = expf(se[l * 4 + h] - mx[h]);
            se[l * 4 + h] = e;
            lsm[h] += e;
        }
    }
#pragma unroll
    for (int h = 0; h < 4; h++) sred[t * 4 + h] = lsm[h];
    __syncthreads();
    for (int s = 256; s > 0; s >>= 1) {
        if (t < s) {
#pragma unroll
            for (int h = 0; h < 4; h++)
                sred[t * 4 + h] += sred[(t + s) * 4 + h];
        }
        __syncthreads();
    }
    float hs0 = sred[0], hs1 = sred[1], hs2 = sred[2], hs3 = sred[3];

    // ---- phase 2: weighted enc sum. thread = (l-chunk c, e-group eg) ----
    int c  = t >> 5;       // 0..15
    int eg = t & 31;       // e4 = eg*4
    ull a[8];              // [h*2 + pair]; pair0 = e (4eg,4eg+1), pair1 = (4eg+2,4eg+3)
#pragma unroll
    for (int j = 0; j < 8; j++) a[j] = 0ull;
    const float* encb = g_enc + (size_t)b * LSTRIDE * HID + eg * 4;
    for (int l = c; l < len; l += 16) {
        float4 wv = *(const float4*)(se + l * 4);
        ulonglong2 ev = *(const ulonglong2*)(encb + (size_t)l * HID);
#pragma unroll
        for (int h = 0; h < 4; h++) {
            float wgt = (h == 0) ? wv.x : (h == 1) ? wv.y : (h == 2) ? wv.z : wv.w;
            ull w2 = pack2(wgt, wgt);
            a[h * 2]     = ffma2(ev.x, w2, a[h * 2]);
            a[h * 2 + 1] = ffma2(ev.y, w2, a[h * 2 + 1]);
        }
    }
    __syncthreads();   // all reads of se done

    // write partials into se region: [(c*32+eg)*16 + h*4 + j]
    float* sp = se;
    {
        float p[16];
#pragma unroll
        for (int h = 0; h < 4; h++) {
            unpack2(a[h * 2],     p[h * 4 + 0], p[h * 4 + 1]);
            unpack2(a[h * 2 + 1], p[h * 4 + 2], p[h * 4 + 3]);
        }
        float* dst = sp + (c * 32 + eg) * 16;
#pragma unroll
        for (int h = 0; h < 4; h++)
            *(float4*)(dst + h * 4) = make_float4(p[h * 4], p[h * 4 + 1], p[h * 4 + 2], p[h * 4 + 3]);
    }
    __syncthreads();

    // combine 16 chunk-partials and write out
    if (t < 128) {
        int h   = t >> 5;
        int eg2 = t & 31;
        float4 r = make_float4(0.f, 0.f, 0.f, 0.f);
        for (int c2 = 0; c2 < 16; c2++) {
            float4 v = *(const float4*)(sp + (c2 * 32 + eg2) * 16 + h * 4);
            r.x += v.x; r.y += v.y; r.z += v.z; r.w += v.w;
        }
        float hsv = (h == 0) ? hs0 : (h == 1) ? hs1 : (h == 2) ? hs2 : hs3;
        float inv = 1.f / hsv;
        r.x *= inv; r.y *= inv; r.z *= inv; r.w *= inv;
        *(float4*)(out + b * 512 + h * 128 + eg2 * 4) = r;
    }
}

// ---------------------------------------------------------------------------
extern "C" void kernel_launch(void* const* d_in, const int* in_sizes, int n_in,
                              void* d_out, int out_size)
{
    const float* times    = (const float*)d_in[0];
    const int*   time_ptr = (const int*)  d_in[1];
    const float* X        = (const float*)d_in[2];
    const int*   M        = (const int*)  d_in[3];
    const int*   obs_idx  = (const int*)  d_in[4];
    const float* W0 = (const float*)d_in[6];
    const float* b0 = (const float*)d_in[7];
    const float* W1 = (const float*)d_in[8];
    const float* b1 = (const float*)d_in[9];
    const float* W2 = (const float*)d_in[10];
    const float* b2 = (const float*)d_in[11];
    const float* Wq = (const float*)d_in[12];
    const float* bq = (const float*)d_in[13];
    const float* Wk = (const float*)d_in[14];
    const float* bk = (const float*)d_in[15];

    int R       = in_sizes[0];
    int n_times = in_sizes[0];
    int V       = in_sizes[2] / R;
    int B       = in_sizes[5];

    k_gather<<<B, 256>>>(times, time_ptr, X, M, obs_idx, R, V, n_times);
    k_last<<<1, 32>>>(B);
    k_mlp<<<B * 64 + 1, 128>>>(W0, b0, W1, b1, W2, b2, Wk, bk, Wq, bq, B);
    k_attn<<<B, 512>>>((float*)d_out);
}

// round 5
// speedup vs baseline: 1.1669x; 1.0004x over previous
#include <cuda_runtime.h>
#include <math.h>

// ---------------------------------------------------------------------------
// SeFT network, round 3:
//  - gather (unchanged)
//  - fused MLP 34->128->128->128 + K/Q projection, f32x2 FFMA, wider weight
//    prefetch window, packed smem epilogue stores; query path = block 0
//    (k_last folded in)
//  - attention split: k_score (B x 16 blocks, coalesced kT) writes raw scores;
//    k_attnsum (B*H blocks, 512 thr) does softmax + weighted enc sum
// ---------------------------------------------------------------------------

#define BMAX    32
#define LSTRIDE 2048
#define HID     128
#define NIN     34
#define ASTR    36

typedef unsigned long long ull;

__device__ float g_St[BMAX * LSTRIDE];
__device__ float g_Sc[BMAX * LSTRIDE];
__device__ float g_Sx[BMAX * LSTRIDE];
__device__ int   g_lens[BMAX];
__device__ int   g_maxlen;
__device__ float g_enc[(size_t)BMAX * LSTRIDE * HID];   // [b][l][e]
__device__ float g_kT [(size_t)BMAX * HID * LSTRIDE];   // [b][e][l]
__device__ float g_q  [BMAX * HID];
__device__ float g_sc [(size_t)BMAX * 4 * LSTRIDE];     // [b][h][l] raw scores

// ---- packed fp32x2 helpers -------------------------------------------------
__device__ __forceinline__ ull pack2(float x, float y) {
    ull r;
    asm("mov.b64 %0, {%1, %2};" : "=l"(r) : "f"(x), "f"(y));
    return r;
}
__device__ __forceinline__ void unpack2(ull v, float& lo, float& hi) {
    asm("mov.b64 {%0, %1}, %2;" : "=f"(lo), "=f"(hi) : "l"(v));
}
__device__ __forceinline__ ull ffma2(ull a, ull b, ull c) {
    ull d;
    asm("fma.rn.f32x2 %0, %1, %2, %3;" : "=l"(d) : "l"(a), "l"(b), "l"(c));
    return d;
}

// ---------------------------------------------------------------------------
// Kernel 1: gather (unchanged — known correct)
// ---------------------------------------------------------------------------
__global__ void k_gather(const float* __restrict__ times,
                         const int*   __restrict__ time_ptr,
                         const float* __restrict__ X,
                         const int*   __restrict__ M,
                         const int*   __restrict__ obs_idx,
                         int R, int V, int n_times)
{
    int b = blockIdx.x;
    int t = threadIdx.x;
    int total = R * V;
    int per = (total + 255) / 256;
    int s = t * per;
    int e = min(s + per, total);

    int cnt = 0;
    {
        int r = (s < total) ? (s / V) : 0;
        int c = (s < total) ? (s - r * V) : 0;
        for (int f = s; f < e; f++) {
            if (obs_idx[r] == b && M[f] != 0) cnt++;
            if (++c == V) { c = 0; r++; }
        }
    }

    __shared__ int sc[256];
    sc[t] = cnt;
    __syncthreads();
    for (int off = 1; off < 256; off <<= 1) {
        int v = (t >= off) ? sc[t - off] : 0;
        __syncthreads();
        sc[t] += v;
        __syncthreads();
    }
    int pos = sc[t] - cnt;
    int tot = sc[255];

    {
        int r = (s < total) ? (s / V) : 0;
        int c = (s < total) ? (s - r * V) : 0;
        for (int f = s; f < e; f++) {
            if (obs_idx[r] == b && M[f] != 0) {
                if (pos < LSTRIDE) {
                    int lo = 0, hi = n_times - 1;
                    while (lo < hi) {
                        int mid = (lo + hi + 1) >> 1;
                        if (time_ptr[mid] <= r) lo = mid; else hi = mid - 1;
                    }
                    g_St[b * LSTRIDE + pos] = times[lo];
                    g_Sc[b * LSTRIDE + pos] = (float)c;
                    g_Sx[b * LSTRIDE + pos] = X[f];
                }
                pos++;
            }
            if (++c == V) { c = 0; r++; }
        }
    }

    if (t == 0) {
        int L = min(tot, LSTRIDE);
        g_lens[b] = L;
        atomicMax(&g_maxlen, L);   // idempotent across replays
    }
}

// ---------------------------------------------------------------------------
// 128->128 dense layer, f32x2. Thread tid owns output row `tid`.
// sIn is [k][obs] with row stride ASTR floats. acc[j] holds obs (2j, 2j+1).
// unroll 8 -> 8 independent weight LDG.128 in flight.
// ---------------------------------------------------------------------------
__device__ __forceinline__ void gemm128x2(const float* __restrict__ W,
                                          const float* __restrict__ bias,
                                          const float* sIn, ull acc[16], int tid)
{
    float bb = __ldg(&bias[tid]);
    ull b2 = pack2(bb, bb);
#pragma unroll
    for (int j = 0; j < 16; j++) acc[j] = b2;
    const float4* Wr = (const float4*)(W + tid * HID);
#pragma unroll 8
    for (int k0 = 0; k0 < HID / 4; k0++) {
        float4 w4 = __ldg(&Wr[k0]);
        const float* r0 = sIn + (k0 * 4) * ASTR;
#pragma unroll
        for (int j = 0; j < 4; j++) {
            float wj = (j == 0) ? w4.x : (j == 1) ? w4.y : (j == 2) ? w4.z : w4.w;
            ull w2 = pack2(wj, wj);
            const ulonglong2* row = (const ulonglong2*)(r0 + j * ASTR);
#pragma unroll
            for (int p = 0; p < 8; p++) {
                ulonglong2 v = row[p];
                acc[2 * p]     = ffma2(v.x, w2, acc[2 * p]);
                acc[2 * p + 1] = ffma2(v.y, w2, acc[2 * p + 1]);
            }
        }
    }
}

// packed relu epilogue into [k][obs] smem (8B stores, half the STS count)
__device__ __forceinline__ void store_relu(float* dst, ull acc[16])
{
#pragma unroll
    for (int j = 0; j < 16; j++) {
        float lo, hi; unpack2(acc[j], lo, hi);
        *(ull*)(dst + 2 * j) = pack2(fmaxf(lo, 0.f), fmaxf(hi, 0.f));
    }
}

// ---------------------------------------------------------------------------
// Kernel 2: fused MLP + projection, 32-obs tiles, f32x2.
// Block 0 = query path (computes lastfeat inline; Wq -> g_q).
// ---------------------------------------------------------------------------
__global__ __launch_bounds__(128) void k_mlp(
    const float* __restrict__ W0, const float* __restrict__ b0,
    const float* __restrict__ W1, const float* __restrict__ b1,
    const float* __restrict__ W2, const float* __restrict__ b2,
    const float* __restrict__ Wk, const float* __restrict__ bk,
    const float* __restrict__ Wq, const float* __restrict__ bq,
    int B)
{
    __shared__ __align__(16) float sf[NIN * ASTR];
    __shared__ __align__(16) float sA[HID * ASTR];
    __shared__ __align__(16) float sB[HID * ASTR];
    float* sW0 = sB;   // W0 staged here; consumed in layer0, overwritten later

    int tid = threadIdx.x;
    bool special = (blockIdx.x == 0);
    int b = 0, l0 = 0, nv = 0;
    if (!special) {
        int bi = blockIdx.x - 1;
        b = bi >> 6;
        int lt = bi & 63;
        int len = g_lens[b];
        l0 = lt * 32;
        if (l0 >= len) return;
        nv = min(32, len - l0);
    } else {
        nv = min(B, 32);
    }

    // cooperative coalesced preload of W0 into smem
    {
        const float4* src = (const float4*)W0;
        float4* dst = (float4*)sW0;
        for (int i = tid; i < (HID * NIN) / 4; i += 128) dst[i] = __ldg(&src[i]);
    }

    // features into [k][obs] layout
    if (tid < 32) {
        int o = tid;
        float tv = 0.f, cv = 0.f, xv = 0.f;
        if (special) {
            // inline k_last: pad features unless this patient fills pos L-1
            int L = g_maxlen;
            if (o < nv && L >= 1 && g_lens[o] == L) {
                tv = g_St[o * LSTRIDE + L - 1];
                cv = g_Sc[o * LSTRIDE + L - 1];
                xv = g_Sx[o * LSTRIDE + L - 1];
            }
        } else if (o < nv) {
            tv = g_St[b * LSTRIDE + l0 + o];
            cv = g_Sc[b * LSTRIDE + l0 + o];
            xv = g_Sx[b * LSTRIDE + l0 + o];
        }
#pragma unroll
        for (int i = 0; i < 16; i++) {
            float ts = powf(100.0f, (float)i * (1.0f / 15.0f));
            float sn, cs;
            sincosf(tv / ts, &sn, &cs);
            sf[i * ASTR + o]        = sn;
            sf[(16 + i) * ASTR + o] = cs;
        }
        sf[32 * ASTR + o] = cv;
        sf[33 * ASTR + o] = xv;
    }
    __syncthreads();

    ull acc[16];

    // ---- layer 0: 34 -> 128, relu ----
    {
        float bb = __ldg(&b0[tid]);
        ull b2 = pack2(bb, bb);
#pragma unroll
        for (int j = 0; j < 16; j++) acc[j] = b2;
#pragma unroll 2
        for (int k = 0; k < NIN; k++) {
            float w = sW0[tid * NIN + k];
            ull w2 = pack2(w, w);
            const ulonglong2* row = (const ulonglong2*)(sf + k * ASTR);
#pragma unroll
            for (int p = 0; p < 8; p++) {
                ulonglong2 v = row[p];
                acc[2 * p]     = ffma2(v.x, w2, acc[2 * p]);
                acc[2 * p + 1] = ffma2(v.y, w2, acc[2 * p + 1]);
            }
        }
        store_relu(sA + tid * ASTR, acc);
    }
    __syncthreads();

    // ---- layer 1: 128 -> 128, relu ---- (overwrites sW0 alias; L0 done)
    gemm128x2(W1, b1, sA, acc, tid);
    store_relu(sB + tid * ASTR, acc);
    __syncthreads();

    // ---- layer 2 (enc): 128 -> 128, linear ----
    gemm128x2(W2, b2, sB, acc, tid);
    {
        float v[32];
#pragma unroll
        for (int j = 0; j < 16; j++) unpack2(acc[j], v[2 * j], v[2 * j + 1]);
        float* dst = sA + tid * ASTR;
#pragma unroll
        for (int j = 0; j < 16; j++) *(ull*)(dst + 2 * j) = acc[j];
        if (!special) {
            for (int o = 0; o < nv; o++)
                g_enc[((size_t)b * LSTRIDE + l0 + o) * HID + tid] = v[o];
        }
    }
    __syncthreads();

    // ---- projection: Wk (normal) or Wq (special) ----
    gemm128x2(special ? Wq : Wk, special ? bq : bk, sA, acc, tid);
    {
        float v[32];
#pragma unroll
        for (int j = 0; j < 16; j++) unpack2(acc[j], v[2 * j], v[2 * j + 1]);
        if (special) {
            for (int o = 0; o < nv; o++) g_q[o * HID + tid] = v[o];
        } else {
            float* gk = g_kT + ((size_t)b * HID + tid) * LSTRIDE + l0;
#pragma unroll
            for (int o = 0; o < 32; o += 4) {
                if (o + 4 <= nv) {
                    *(float4*)(gk + o) = make_float4(v[o], v[o + 1], v[o + 2], v[o + 3]);
                } else {
                    for (int j = 0; j < 4; j++)
                        if (o + j < nv) gk[o + j] = v[o + j];
                }
            }
        }
    }
}

// ---------------------------------------------------------------------------
// Kernel 3: raw attention scores. grid (B, LSTRIDE/128), block 128.
// Thread t owns l = lc*128 + t; dot over e is coalesced across the warp.
// ---------------------------------------------------------------------------
__global__ __launch_bounds__(128) void k_score()
{
    int b  = blockIdx.x;
    int lc = blockIdx.y;
    int tid = threadIdx.x;
    int len = min(g_lens[b], LSTRIDE);
    int l = lc * 128 + tid;

    __shared__ float sq[HID];
    if (tid < HID) sq[tid] = g_q[b * HID + tid];
    __syncthreads();

    if (l >= len) return;

    const float scale = 0.17677669529663687f; // 1/sqrt(32)
    const float* kb = g_kT + (size_t)b * HID * LSTRIDE + l;

    float a[4] = {0.f, 0.f, 0.f, 0.f};
#pragma unroll
    for (int h = 0; h < 4; h++) {
#pragma unroll 8
        for (int e2 = 0; e2 < 32; e2++) {
            int e = h * 32 + e2;
            a[h] = fmaf(__ldg(&kb[(size_t)e * LSTRIDE]), sq[e], a[h]);
        }
    }
#pragma unroll
    for (int h = 0; h < 4; h++)
        g_sc[((size_t)b * 4 + h) * LSTRIDE + l] = a[h] * scale;
}

// ---------------------------------------------------------------------------
// Kernel 4: softmax + weighted enc sum. grid B*4 (one block per (b,h)),
// 512 threads = 4 l-stripes x 128 e.
// ---------------------------------------------------------------------------
__global__ __launch_bounds__(512) void k_attnsum(float* __restrict__ out)
{
    int b = blockIdx.x >> 2;
    int h = blockIdx.x & 3;
    int t = threadIdx.x;
    int len = min(g_lens[b], LSTRIDE);

    __shared__ __align__(16) float ssc[LSTRIDE];
    __shared__ float sred[512];
    __shared__ float sp[4 * 128];

    if (len == 0) {
        if (t < 128) out[b * 512 + h * 128 + t] = 0.f;
        return;
    }

    const float* scr = g_sc + ((size_t)b * 4 + h) * LSTRIDE;

    // load scores + local max
    float lmx = -1e30f;
    for (int l = t; l < len; l += 512) {
        float s = __ldg(&scr[l]);
        ssc[l] = s;
        lmx = fmaxf(lmx, s);
    }
    sred[t] = lmx;
    __syncthreads();
    for (int s = 256; s > 0; s >>= 1) {
        if (t < s) sred[t] = fmaxf(sred[t], sred[t + s]);
        __syncthreads();
    }
    float mx = sred[0];
    __syncthreads();

    // exp + sum
    float lsm = 0.f;
    for (int l = t; l < len; l += 512) {
        float e = expf(ssc[l] - mx);
        ssc[l] = e;
        lsm += e;
    }
    sred[t] = lsm;
    __syncthreads();
    for (int s = 256; s > 0; s >>= 1) {
        if (t < s) sred[t] += sred[t + s];
        __syncthreads();
    }
    float inv = 1.f / sred[0];

    // weighted enc sum: stripe c over l, element e
    int c = t >> 7;      // 0..3
    int e = t & 127;
    const float* encb = g_enc + (size_t)b * LSTRIDE * HID + e;
    float a0 = 0.f, a1 = 0.f;
    int l = c;
    for (; l + 4 < len; l += 8) {
        a0 = fmaf(ssc[l],     __ldg(&encb[(size_t)l * HID]),       a0);
        a1 = fmaf(ssc[l + 4], __ldg(&encb[(size_t)(l + 4) * HID]), a1);
    }
    if (l < len) a0 = fmaf(ssc[l], __ldg(&encb[(size_t)l * HID]), a0);
    sp[c * 128 + e] = a0 + a1;
    __syncthreads();

    if (t < 128) {
        float r = (sp[t] + sp[128 + t]) + (sp[256 + t] + sp[384 + t]);
        out[b * 512 + h * 128 + t] = r * inv;
    }
}

// ---------------------------------------------------------------------------
extern "C" void kernel_launch(void* const* d_in, const int* in_sizes, int n_in,
                              void* d_out, int out_size)
{
    const float* times    = (const float*)d_in[0];
    const int*   time_ptr = (const int*)  d_in[1];
    const float* X        = (const float*)d_in[2];
    const int*   M        = (const int*)  d_in[3];
    const int*   obs_idx  = (const int*)  d_in[4];
    const float* W0 = (const float*)d_in[6];
    const float* b0 = (const float*)d_in[7];
    const float* W1 = (const float*)d_in[8];
    const float* b1 = (const float*)d_in[9];
    const float* W2 = (const float*)d_in[10];
    const float* b2 = (const float*)d_in[11];
    const float* Wq = (const float*)d_in[12];
    const float* bq = (const float*)d_in[13];
    const float* Wk = (const float*)d_in[14];
    const float* bk = (const float*)d_in[15];

    int R       = in_sizes[0];
    int n_times = in_sizes[0];
    int V       = in_sizes[2] / R;
    int B       = in_sizes[5];

    k_gather<<<B, 256>>>(times, time_ptr, X, M, obs_idx, R, V, n_times);
    k_mlp<<<B * 64 + 1, 128>>>(W0, b0, W1, b1, W2, b2, Wk, bk, Wq, bq, B);
    dim3 gs(B, LSTRIDE / 128);
    k_score<<<gs, 128>>>();
    k_attnsum<<<B * 4, 512>>>((float*)d_out);
}

// round 6
// speedup vs baseline: 3.6410x; 3.1201x over previous
#include <cuda_runtime.h>
#include <math.h>

// ---------------------------------------------------------------------------
// SeFT network, round 5:
//  - gather rewritten as coalesced ballot compaction (k_rows + k_compact)
//  - k_mlp: smem-staged weight chunks (aliased into dead output buffer),
//    2 output rows per thread, f32x2 FFMA -> FMA-pipe bound
//  - attention fused: per-(b,h) block computes scores + softmax + enc sum
// ---------------------------------------------------------------------------

#define BMAX    32
#define LSTRIDE 2048
#define HID     128
#define NIN     34
#define ASTR    36          // activation row stride (floats), 144B = 16B-aligned

typedef unsigned long long ull;

__device__ float    g_St[BMAX * LSTRIDE];
__device__ float    g_Sc[BMAX * LSTRIDE];
__device__ float    g_Sx[BMAX * LSTRIDE];
__device__ int      g_lens[BMAX];
__device__ int      g_maxlen;
__device__ int      g_rowcnt[4096];
__device__ unsigned g_rowmask[4096];
__device__ float    g_rowtime[4096];
__device__ float    g_enc[(size_t)BMAX * LSTRIDE * HID];   // [b][l][e]
__device__ float    g_kT [(size_t)BMAX * HID * LSTRIDE];   // [b][e][l]
__device__ float    g_q  [BMAX * HID];

// ---- packed fp32x2 helpers -------------------------------------------------
__device__ __forceinline__ ull pack2(float x, float y) {
    ull r;
    asm("mov.b64 %0, {%1, %2};" : "=l"(r) : "f"(x), "f"(y));
    return r;
}
__device__ __forceinline__ void unpack2(ull v, float& lo, float& hi) {
    asm("mov.b64 {%0, %1}, %2;" : "=f"(lo), "=f"(hi) : "l"(v));
}
__device__ __forceinline__ ull ffma2(ull a, ull b, ull c) {
    ull d;
    asm("fma.rn.f32x2 %0, %1, %2, %3;" : "=l"(d) : "l"(a), "l"(b), "l"(c));
    return d;
}

// ---------------------------------------------------------------------------
// Kernel 1: per-row nonzero mask/count/time. One warp per row, coalesced.
// (V <= 32 in this problem.)
// ---------------------------------------------------------------------------
__global__ void k_rows(const float* __restrict__ times,
                       const int*   __restrict__ time_ptr,
                       const int*   __restrict__ M,
                       int R, int V, int n_times)
{
    int w = (blockIdx.x * blockDim.x + threadIdx.x) >> 5;
    int lane = threadIdx.x & 31;
    if (w >= R) return;
    int m = 0;
    if (lane < V) m = (M[w * V + lane] != 0);
    unsigned mask = __ballot_sync(0xffffffffu, m);
    if (lane == 0) {
        g_rowmask[w] = mask;
        g_rowcnt[w]  = __popc(mask);
        int lo = 0, hi = n_times - 1;
        while (lo < hi) {
            int mid = (lo + hi + 1) >> 1;
            if (time_ptr[mid] <= w) lo = mid; else hi = mid - 1;
        }
        g_rowtime[w] = times[lo];
    }
}

// ---------------------------------------------------------------------------
// Kernel 2: per-patient compaction. Block b scans its rpp rows (contiguous by
// construction: obs_idx = repeat(arange(B))), smem-prefix of row counts,
// warp-per-row scatter of (t, col, val). 256 threads. rpp <= 256.
// ---------------------------------------------------------------------------
__global__ void k_compact(const float* __restrict__ X, int R, int V, int B)
{
    int b = blockIdx.x;
    int rpp = R / B;
    int r0 = b * rpp;
    int t = threadIdx.x;

    __shared__ int ssum[256];
    __shared__ int sstart[256];
    int cnt = (t < rpp) ? g_rowcnt[r0 + t] : 0;
    ssum[t] = cnt;
    __syncthreads();
    for (int off = 1; off < 256; off <<= 1) {
        int v = (t >= off) ? ssum[t - off] : 0;
        __syncthreads();
        ssum[t] += v;
        __syncthreads();
    }
    int tot = ssum[255];
    sstart[t] = ssum[t] - cnt;
    __syncthreads();

    int lane = t & 31, w = t >> 5;
    for (int lr = w; lr < rpp; lr += 8) {
        int r = r0 + lr;
        unsigned mask = g_rowmask[r];
        float tv = g_rowtime[r];
        int start = sstart[lr];
        if (lane < V && ((mask >> lane) & 1u)) {
            int pos = start + __popc(mask & ((1u << lane) - 1u));
            if (pos < LSTRIDE) {
                g_St[b * LSTRIDE + pos] = tv;
                g_Sc[b * LSTRIDE + pos] = (float)lane;
                g_Sx[b * LSTRIDE + pos] = X[r * V + lane];
            }
        }
    }
    if (t == 0) {
        int L = min(tot, LSTRIDE);
        g_lens[b] = L;
        atomicMax(&g_maxlen, L);   // idempotent across replays
    }
}

// ---------------------------------------------------------------------------
// 128->128 dense layer, f32x2, weights staged in smem chunks of 32 k-rows.
// Thread (r = t&63, h = t>>6) computes output rows r and r+64 for the 16
// observations [h*16, h*16+16). wbuf aliases a dead smem buffer; layout
// wbuf[kk*129 + o] (conflict-free for both staging stores and compute loads).
// ---------------------------------------------------------------------------
__device__ __forceinline__ void dense128(const float* __restrict__ W,
                                         const float* __restrict__ bias,
                                         const float* sIn, float* wbuf,
                                         ull accA[8], ull accB[8],
                                         int r, int h, int tid)
{
    float bA = __ldg(&bias[r]);
    float bB = __ldg(&bias[r + 64]);
    ull iA = pack2(bA, bA), iB = pack2(bB, bB);
#pragma unroll
    for (int j = 0; j < 8; j++) { accA[j] = iA; accB[j] = iB; }

    for (int c = 0; c < 4; c++) {
        // stage 128x32 chunk, coalesced LDG.128, conflict-free STS
        for (int i4 = tid; i4 < 1024; i4 += 128) {
            int e  = i4 << 2;        // element index within chunk = o*32 + kk
            int o  = e >> 5;
            int kk = e & 31;
            float4 v = __ldg((const float4*)(W + o * HID + c * 32 + kk));
            wbuf[kk * 129 + o]       = v.x;
            wbuf[(kk + 1) * 129 + o] = v.y;
            wbuf[(kk + 2) * 129 + o] = v.z;
            wbuf[(kk + 3) * 129 + o] = v.w;
        }
        __syncthreads();
#pragma unroll 4
        for (int kk = 0; kk < 32; kk++) {
            float wA = wbuf[kk * 129 + r];
            float wB = wbuf[kk * 129 + 64 + r];
            ull wA2 = pack2(wA, wA), wB2 = pack2(wB, wB);
            const ulonglong2* row =
                (const ulonglong2*)(sIn + (c * 32 + kk) * ASTR + h * 16);
#pragma unroll
            for (int p = 0; p < 4; p++) {
                ulonglong2 v = row[p];
                accA[2 * p]     = ffma2(v.x, wA2, accA[2 * p]);
                accA[2 * p + 1] = ffma2(v.y, wA2, accA[2 * p + 1]);
                accB[2 * p]     = ffma2(v.x, wB2, accB[2 * p]);
                accB[2 * p + 1] = ffma2(v.y, wB2, accB[2 * p + 1]);
            }
        }
        __syncthreads();
    }
}

// relu epilogue into [k][obs] smem for rows r, r+64, obs half h
__device__ __forceinline__ void epi_relu(float* dst, ull accA[8], ull accB[8],
                                         int r, int h)
{
    float* dA = dst + r * ASTR + h * 16;
    float* dB = dst + (r + 64) * ASTR + h * 16;
#pragma unroll
    for (int j = 0; j < 8; j++) {
        float lo, hi;
        unpack2(accA[j], lo, hi);
        *(ull*)(dA + 2 * j) = pack2(fmaxf(lo, 0.f), fmaxf(hi, 0.f));
        unpack2(accB[j], lo, hi);
        *(ull*)(dB + 2 * j) = pack2(fmaxf(lo, 0.f), fmaxf(hi, 0.f));
    }
}

// ---------------------------------------------------------------------------
// Kernel 3: fused MLP + projection, 32-obs tiles.
// Block 0 = query path (lastfeat inline, Wq -> g_q). Others: enc + kT.
// Buffer plan (weights staged into the dead/output buffer of each layer):
//   L0: in sf, w sA, out sA      L1: in sA, w sB, out sB
//   L2: in sB, w sA, out sA+enc  Pr: in sA, w sB, out global
// ---------------------------------------------------------------------------
__global__ __launch_bounds__(128) void k_mlp(
    const float* __restrict__ W0, const float* __restrict__ b0,
    const float* __restrict__ W1, const float* __restrict__ b1,
    const float* __restrict__ W2, const float* __restrict__ b2,
    const float* __restrict__ Wk, const float* __restrict__ bk,
    const float* __restrict__ Wq, const float* __restrict__ bq,
    int B)
{
    __shared__ __align__(16) float sf[NIN * ASTR];
    __shared__ __align__(16) float sA[HID * ASTR];
    __shared__ __align__(16) float sB[HID * ASTR];

    int tid = threadIdx.x;
    int r = tid & 63;
    int h = tid >> 6;

    bool special = (blockIdx.x == 0);
    int b = 0, l0 = 0, nv = 0;
    if (!special) {
        int bi = blockIdx.x - 1;
        b = bi >> 6;
        int lt = bi & 63;
        int len = g_lens[b];
        l0 = lt * 32;
        if (l0 >= len) return;
        nv = min(32, len - l0);
    } else {
        nv = min(B, 32);
    }

    // stage W0 [128][34] into sA at stride 129 (dead until L0 epilogue)
    for (int i = tid; i < HID * NIN; i += 128) {
        int o = i / NIN, k = i - o * NIN;
        sA[k * 129 + o] = __ldg(&W0[i]);
    }

    // features into [k][obs] layout
    if (tid < 32) {
        int o = tid;
        float tv = 0.f, cv = 0.f, xv = 0.f;
        if (special) {
            int L = g_maxlen;
            if (o < nv && L >= 1 && g_lens[o] == L) {
                tv = g_St[o * LSTRIDE + L - 1];
                cv = g_Sc[o * LSTRIDE + L - 1];
                xv = g_Sx[o * LSTRIDE + L - 1];
            }
        } else if (o < nv) {
            tv = g_St[b * LSTRIDE + l0 + o];
            cv = g_Sc[b * LSTRIDE + l0 + o];
            xv = g_Sx[b * LSTRIDE + l0 + o];
        }
#pragma unroll
        for (int i = 0; i < 16; i++) {
            float ts = powf(100.0f, (float)i * (1.0f / 15.0f));
            float sn, cs;
            sincosf(tv / ts, &sn, &cs);
            sf[i * ASTR + o]        = sn;
            sf[(16 + i) * ASTR + o] = cs;
        }
        sf[32 * ASTR + o] = cv;
        sf[33 * ASTR + o] = xv;
    }
    __syncthreads();

    ull accA[8], accB[8];

    // ---- layer 0: 34 -> 128, relu (weights in sA, input sf) ----
    {
        float bA = __ldg(&b0[r]);
        float bB = __ldg(&b0[r + 64]);
        ull iA = pack2(bA, bA), iB = pack2(bB, bB);
#pragma unroll
        for (int j = 0; j < 8; j++) { accA[j] = iA; accB[j] = iB; }
#pragma unroll 2
        for (int k = 0; k < NIN; k++) {
            float wA = sA[k * 129 + r];
            float wB = sA[k * 129 + 64 + r];
            ull wA2 = pack2(wA, wA), wB2 = pack2(wB, wB);
            const ulonglong2* row = (const ulonglong2*)(sf + k * ASTR + h * 16);
#pragma unroll
            for (int p = 0; p < 4; p++) {
                ulonglong2 v = row[p];
                accA[2 * p]     = ffma2(v.x, wA2, accA[2 * p]);
                accA[2 * p + 1] = ffma2(v.y, wA2, accA[2 * p + 1]);
                accB[2 * p]     = ffma2(v.x, wB2, accB[2 * p]);
                accB[2 * p + 1] = ffma2(v.y, wB2, accB[2 * p + 1]);
            }
        }
        __syncthreads();            // weights in sA dead after this
        epi_relu(sA, accA, accB, r, h);
    }
    __syncthreads();

    // ---- layer 1: 128 -> 128, relu (in sA, weights+out sB) ----
    dense128(W1, b1, sA, sB, accA, accB, r, h, tid);
    epi_relu(sB, accA, accB, r, h);
    __syncthreads();

    // ---- layer 2 (enc): 128 -> 128, linear (in sB, weights+out sA) ----
    dense128(W2, b2, sB, sA, accA, accB, r, h, tid);
    {
        float vA[16], vB[16];
#pragma unroll
        for (int j = 0; j < 8; j++) {
            unpack2(accA[j], vA[2 * j], vA[2 * j + 1]);
            unpack2(accB[j], vB[2 * j], vB[2 * j + 1]);
        }
        float* dA = sA + r * ASTR + h * 16;
        float* dB = sA + (r + 64) * ASTR + h * 16;
#pragma unroll
        for (int j = 0; j < 8; j++) {
            *(ull*)(dA + 2 * j) = accA[j];
            *(ull*)(dB + 2 * j) = accB[j];
        }
        if (!special) {
#pragma unroll
            for (int o = 0; o < 16; o++) {
                int og = h * 16 + o;
                if (og < nv) {
                    size_t base = ((size_t)b * LSTRIDE + l0 + og) * HID;
                    g_enc[base + r]      = vA[o];
                    g_enc[base + 64 + r] = vB[o];
                }
            }
        }
    }
    __syncthreads();

    // ---- projection: Wk (normal) or Wq (special); in sA, weights sB ----
    dense128(special ? Wq : Wk, special ? bq : bk, sA, sB, accA, accB, r, h, tid);
    {
        float vA[16], vB[16];
#pragma unroll
        for (int j = 0; j < 8; j++) {
            unpack2(accA[j], vA[2 * j], vA[2 * j + 1]);
            unpack2(accB[j], vB[2 * j], vB[2 * j + 1]);
        }
        if (special) {
#pragma unroll
            for (int o = 0; o < 16; o++) {
                int og = h * 16 + o;
                if (og < nv) {
                    g_q[og * HID + r]      = vA[o];
                    g_q[og * HID + 64 + r] = vB[o];
                }
            }
        } else {
            float* gkA = g_kT + ((size_t)b * HID + r) * LSTRIDE + l0 + h * 16;
            float* gkB = g_kT + ((size_t)b * HID + 64 + r) * LSTRIDE + l0 + h * 16;
#pragma unroll
            for (int o = 0; o < 16; o += 4) {
                int og = h * 16 + o;
                if (og + 4 <= nv) {
                    *(float4*)(gkA + o) = make_float4(vA[o], vA[o+1], vA[o+2], vA[o+3]);
                    *(float4*)(gkB + o) = make_float4(vB[o], vB[o+1], vB[o+2], vB[o+3]);
                } else {
                    for (int m = 0; m < 4; m++)
                        if (og + m < nv) { gkA[o + m] = vA[o + m]; gkB[o + m] = vB[o + m]; }
                }
            }
        }
    }
}

// ---------------------------------------------------------------------------
// Kernel 4: fused attention. One block per (b, h), 512 threads.
// Scores from transposed K (coalesced over l), softmax, weighted enc sum.
// ---------------------------------------------------------------------------
__global__ __launch_bounds__(512) void k_attn(float* __restrict__ out)
{
    int b  = blockIdx.x >> 2;
    int hh = blockIdx.x & 3;
    int t  = threadIdx.x;
    int len = min(g_lens[b], LSTRIDE);

    __shared__ float sq[32];
    __shared__ __align__(16) float ssc[LSTRIDE];
    __shared__ float sred[512];
    __shared__ float sp[4 * 128];

    if (t < 32) sq[t] = g_q[b * HID + hh * 32 + t];
    __syncthreads();

    if (len == 0) {
        if (t < 128) out[b * 512 + hh * 128 + t] = 0.f;
        return;
    }

    const float scale = 0.17677669529663687f; // 1/sqrt(32)
    const float* kb = g_kT + ((size_t)b * HID + hh * 32) * LSTRIDE;

    // scores + local max (coalesced over l)
    float lmx = -1e30f;
    for (int l = t; l < len; l += 512) {
        float s = 0.f;
#pragma unroll 8
        for (int e = 0; e < 32; e++)
            s = fmaf(__ldg(&kb[(size_t)e * LSTRIDE + l]), sq[e], s);
        s *= scale;
        ssc[l] = s;
        lmx = fmaxf(lmx, s);
    }
    sred[t] = lmx;
    __syncthreads();
    for (int s = 256; s > 0; s >>= 1) {
        if (t < s) sred[t] = fmaxf(sred[t], sred[t + s]);
        __syncthreads();
    }
    float mx = sred[0];
    __syncthreads();

    // exp + sum
    float lsm = 0.f;
    for (int l = t; l < len; l += 512) {
        float e = expf(ssc[l] - mx);
        ssc[l] = e;
        lsm += e;
    }
    sred[t] = lsm;
    __syncthreads();
    for (int s = 256; s > 0; s >>= 1) {
        if (t < s) sred[t] += sred[t + s];
        __syncthreads();
    }
    float inv = 1.f / sred[0];

    // weighted enc sum: stripe c over l, element e
    int c = t >> 7;      // 0..3
    int e = t & 127;
    const float* encb = g_enc + (size_t)b * LSTRIDE * HID + e;
    float a0 = 0.f, a1 = 0.f;
    int l = c;
    for (; l + 4 < len; l += 8) {
        a0 = fmaf(ssc[l],     __ldg(&encb[(size_t)l * HID]),       a0);
        a1 = fmaf(ssc[l + 4], __ldg(&encb[(size_t)(l + 4) * HID]), a1);
    }
    if (l < len) a0 = fmaf(ssc[l], __ldg(&encb[(size_t)l * HID]), a0);
    sp[c * 128 + e] = a0 + a1;
    __syncthreads();

    if (t < 128) {
        float r = (sp[t] + sp[128 + t]) + (sp[256 + t] + sp[384 + t]);
        out[b * 512 + hh * 128 + t] = r * inv;
    }
}

// ---------------------------------------------------------------------------
extern "C" void kernel_launch(void* const* d_in, const int* in_sizes, int n_in,
                              void* d_out, int out_size)
{
    const float* times    = (const float*)d_in[0];
    const int*   time_ptr = (const int*)  d_in[1];
    const float* X        = (const float*)d_in[2];
    const int*   M        = (const int*)  d_in[3];
    const float* W0 = (const float*)d_in[6];
    const float* b0 = (const float*)d_in[7];
    const float* W1 = (const float*)d_in[8];
    const float* b1 = (const float*)d_in[9];
    const float* W2 = (const float*)d_in[10];
    const float* b2 = (const float*)d_in[11];
    const float* Wq = (const float*)d_in[12];
    const float* bq = (const float*)d_in[13];
    const float* Wk = (const float*)d_in[14];
    const float* bk = (const float*)d_in[15];

    int R       = in_sizes[0];
    int n_times = in_sizes[0];
    int V       = in_sizes[2] / R;
    int B       = in_sizes[5];

    k_rows<<<(R * 32 + 255) / 256, 256>>>(times, time_ptr, M, R, V, n_times);
    k_compact<<<B, 256>>>(X, R, V, B);
    k_mlp<<<B * 64 + 1, 128>>>(W0, b0, W1, b1, W2, b2, Wk, bk, Wq, bq, B);
    k_attn<<<B * 4, 512>>>((float*)d_out);
}